// round 14
// baseline (speedup 1.0000x reference)
#include <cuda_runtime.h>
#include <cuda_bf16.h>
#include <mma.h>

using namespace nvcuda;

#define NN 50000
#define DD 128
#define EE 600000
#define GG 512
#define LLAYERS 3
#define EDIM 16
#define JKD 384
#define CHUNK 32
#define TROWS 64
#define NT64 ((NN + TROWS - 1) / TROWS)
#define WS 136   // bf16 smem stride (elems)
#define CS 136   // f32 staging stride

typedef unsigned long long u64;
typedef unsigned int u32;

// Scratch (device globals: no runtime allocation allowed)
__device__ float g_xcur[NN * DD];
__device__ float g_agg[NN * DD];           // zeroed by init (call start) / node each layer
__device__ float g_pool[GG * JKD];         // zeroed by head_kernel each call
__device__ int   g_cnt[NN];                // zeroed by init each call (before hist)
__device__ int   g_cursor[NN];
__device__ int   g_csr_src[EE];
__device__ int   g_csr_dst[EE];
__device__ float g_csr_ea[(size_t)EE * EDIM];

// ---------------------------------------------------------------------------
// packed f32x2 helpers
// ---------------------------------------------------------------------------
__device__ __forceinline__ u64 pack2(float x, float y) {
    u64 r; asm("mov.b64 %0, {%1, %2};" : "=l"(r) : "f"(x), "f"(y)); return r;
}
__device__ __forceinline__ float2 unpack2(u64 v) {
    float2 r; asm("mov.b64 {%0, %1}, %2;" : "=f"(r.x), "=f"(r.y) : "l"(v)); return r;
}
__device__ __forceinline__ void fma2(u64& d, u64 a, u64 b) {
    asm("fma.rn.f32x2 %0, %1, %2, %0;" : "+l"(d) : "l"(a), "l"(b));
}
__device__ __forceinline__ void red_v4(float* p, float4 v) {
    asm volatile("red.global.add.v4.f32 [%0], {%1,%2,%3,%4};"
                 :: "l"(p), "f"(v.x), "f"(v.y), "f"(v.z), "f"(v.w) : "memory");
}
__device__ __forceinline__ void red_v2(float* p, float x, float y) {
    asm volatile("red.global.add.v2.f32 [%0], {%1,%2};"
                 :: "l"(p), "f"(x), "f"(y) : "memory");
}

// ---------------------------------------------------------------------------
// init: x_cur = x + vn0; agg = 0; cnt = 0  (launch #1)
// ---------------------------------------------------------------------------
__global__ void init_kernel(const float* __restrict__ x, const float* __restrict__ vn0) {
    int i = blockIdx.x * blockDim.x + threadIdx.x;
    if (i < NN) g_cnt[i] = 0;
    if (i >= NN * DD / 4) return;
    float4 xv = reinterpret_cast<const float4*>(x)[i];
    float4 vv = reinterpret_cast<const float4*>(vn0)[i & 31];
    xv.x += vv.x; xv.y += vv.y; xv.z += vv.z; xv.w += vv.w;
    reinterpret_cast<float4*>(g_xcur)[i] = xv;
    reinterpret_cast<float4*>(g_agg)[i] = make_float4(0.f, 0.f, 0.f, 0.f);
}

// ---------------------------------------------------------------------------
// Layer-0 aggregation: R2-style RED edge kernel (no CSR dependency) so that
// node_l0 can be launch #4 (the one ncu profiles). Weights in registers,
// packed fma2 encoder, software-pipelined edge loop, red.v4 per edge.
// ---------------------------------------------------------------------------
__global__ __launch_bounds__(256, 2) void edge_l0_kernel(
    const int* __restrict__ ei, const float* __restrict__ ea,
    const float* __restrict__ ew, const float* __restrict__ ebias)
{
    const int lane = threadIdx.x & 31;

    u64 w0[EDIM], w1[EDIM];
#pragma unroll
    for (int k = 0; k < EDIM; k++) {
        const float4 wv = *reinterpret_cast<const float4*>(&ew[k * DD + lane * 4]);
        w0[k] = pack2(wv.x, wv.y);
        w1[k] = pack2(wv.z, wv.w);
    }
    const float4 bq = *reinterpret_cast<const float4*>(&ebias[lane * 4]);
    const u64 b0 = pack2(bq.x, bq.y), b1 = pack2(bq.z, bq.w);

    const int warp = (blockIdx.x * blockDim.x + threadIdx.x) >> 5;
    const int nw = (gridDim.x * blockDim.x) >> 5;

    int e = warp;
    if (e >= EE) return;
    int src = ei[e];
    int dst = ei[EE + e];
    float a = (lane < EDIM) ? ea[(size_t)e * EDIM + lane] : 0.f;
    float4 xv = *reinterpret_cast<const float4*>(&g_xcur[(size_t)src * DD + lane * 4]);

    while (true) {
        const int en = e + nw;
        const bool more = en < EE;
        int nsrc = 0, ndst = 0;
        float na = 0.f;
        if (more) {
            nsrc = ei[en];
            ndst = ei[EE + en];
            na = (lane < EDIM) ? ea[(size_t)en * EDIM + lane] : 0.f;
        }

        u64 acc0 = b0, acc1 = b1;
#pragma unroll
        for (int k = 0; k < EDIM; k++) {
            const float ak = __shfl_sync(0xffffffffu, a, k);
            const u64 ak2 = pack2(ak, ak);
            fma2(acc0, ak2, w0[k]);
            fma2(acc1, ak2, w1[k]);
        }

        float4 nxv = make_float4(0.f, 0.f, 0.f, 0.f);
        if (more)
            nxv = *reinterpret_cast<const float4*>(&g_xcur[(size_t)nsrc * DD + lane * 4]);

        const float2 lo = unpack2(acc0), hi = unpack2(acc1);
        float4 m;
        m.x = fmaxf(lo.x + xv.x, 0.f);
        m.y = fmaxf(lo.y + xv.y, 0.f);
        m.z = fmaxf(hi.x + xv.z, 0.f);
        m.w = fmaxf(hi.y + xv.w, 0.f);
        red_v4(&g_agg[(size_t)dst * DD + lane * 4], m);

        if (!more) break;
        e = en; src = nsrc; dst = ndst; a = na; xv = nxv;
    }
}

// ---------------------------------------------------------------------------
// CSR build (hist at launch #3; scan/scatter after node_l0, before agg_l1)
// ---------------------------------------------------------------------------
__global__ void k_hist(const int* __restrict__ ei) {
    int e = blockIdx.x * blockDim.x + threadIdx.x;
    if (e < EE) atomicAdd(&g_cnt[ei[EE + e]], 1);
}

__global__ __launch_bounds__(1024) void k_scan_single() {
    __shared__ int s[1024];
    const int t = threadIdx.x;
    const int per = (NN + 1023) / 1024;
    const int base = t * per;
    int lim = NN - base;
    if (lim < 0) lim = 0;
    if (lim > per) lim = per;
    int loc = 0;
    for (int i = 0; i < lim; i++) loc += g_cnt[base + i];
    s[t] = loc;
    __syncthreads();
#pragma unroll
    for (int o = 1; o < 1024; o <<= 1) {
        int u = (t >= o) ? s[t - o] : 0;
        __syncthreads();
        s[t] += u;
        __syncthreads();
    }
    int run = (t > 0) ? s[t - 1] : 0;
    for (int i = 0; i < lim; i++) {
        const int c = g_cnt[base + i];
        g_cursor[base + i] = run;
        run += c;
    }
}

__global__ void k_scatter(const int* __restrict__ ei, const float* __restrict__ ea) {
    int e = blockIdx.x * blockDim.x + threadIdx.x;
    if (e >= EE) return;
    const int dst = ei[EE + e];
    const int pos = atomicAdd(&g_cursor[dst], 1);
    g_csr_src[pos] = ei[e];
    g_csr_dst[pos] = dst;
    const float4* q = reinterpret_cast<const float4*>(&ea[(size_t)e * EDIM]);
    float4* s = reinterpret_cast<float4*>(&g_csr_ea[(size_t)pos * EDIM]);
    s[0] = q[0]; s[1] = q[1]; s[2] = q[2]; s[3] = q[3];
}

// ---------------------------------------------------------------------------
// Aggregation for layers 1,2 (R8/R11 version, measured 101.5us — unchanged)
// ---------------------------------------------------------------------------
__global__ __launch_bounds__(256, 2) void agg_kernel(
    const float* __restrict__ ew, const float* __restrict__ ebias)
{
    __shared__ float s_attr[8][2][CHUNK * EDIM];
    __shared__ int2  s_sd[8][2][CHUNK];

    const int lane = threadIdx.x & 31;
    const int w = threadIdx.x >> 5;

    u64 wp[8][4];
#pragma unroll
    for (int j = 0; j < 8; j++)
#pragma unroll
        for (int c = 0; c < 4; c++)
            wp[j][c] = pack2(ew[(2 * j) * DD + lane * 4 + c],
                             ew[(2 * j + 1) * DD + lane * 4 + c]);
    const float4 bq = *reinterpret_cast<const float4*>(&ebias[lane * 4]);

    const int warp = (blockIdx.x * blockDim.x + threadIdx.x) >> 5;
    const int nw = (gridDim.x * blockDim.x) >> 5;
    const int epw = (EE + nw - 1) / nw;
    const int beg = warp * epw;
    if (beg >= EE) return;
    const int range = ((beg + epw < EE) ? beg + epw : EE) - beg;
    const int nchunks = (range + CHUNK - 1) / CHUNK;

    {
        const int cnt = (range < CHUNK) ? range : CHUNK;
        const float4* src4 = reinterpret_cast<const float4*>(&g_csr_ea[(size_t)beg * EDIM]);
        float4* dst4 = reinterpret_cast<float4*>(&s_attr[w][0][0]);
        for (int i = lane; i < cnt * 4; i += 32) dst4[i] = src4[i];
        if (lane < cnt) s_sd[w][0][lane] = make_int2(g_csr_src[beg + lane], g_csr_dst[beg + lane]);
    }
    __syncwarp();

    int2 sd0 = s_sd[w][0][0];
    int2 sd1 = (range > 1) ? s_sd[w][0][1] : sd0;
    float4 x0 = *reinterpret_cast<const float4*>(&g_xcur[(size_t)sd0.x * DD + lane * 4]);
    float4 x1 = (range > 1)
        ? *reinterpret_cast<const float4*>(&g_xcur[(size_t)sd1.x * DD + lane * 4]) : x0;

    float4 acc = make_float4(0.f, 0.f, 0.f, 0.f);
    int cur = sd0.y;
    bool firstflush = true;
    int gpos = 0;
    int buf = 0;

    for (int c = 0; c < nchunks; c++) {
        const int cbeg = c * CHUNK;
        const int cnt = ((range - cbeg) < CHUNK) ? (range - cbeg) : CHUNK;

        __syncwarp();
        if (c + 1 < nchunks) {
            const int nbeg = beg + cbeg + CHUNK;
            const int ncnt = ((range - cbeg - CHUNK) < CHUNK) ? (range - cbeg - CHUNK) : CHUNK;
            const float4* src4 = reinterpret_cast<const float4*>(&g_csr_ea[(size_t)nbeg * EDIM]);
            float4* dst4 = reinterpret_cast<float4*>(&s_attr[w][buf ^ 1][0]);
            for (int i = lane; i < ncnt * 4; i += 32) dst4[i] = src4[i];
            if (lane < ncnt)
                s_sd[w][buf ^ 1][lane] = make_int2(g_csr_src[nbeg + lane], g_csr_dst[nbeg + lane]);
        }
        __syncwarp();

        for (int i = 0; i < cnt; i++) {
            int2 sd2 = sd1;
            float4 x2 = make_float4(0.f, 0.f, 0.f, 0.f);
            if (gpos + 2 < range) {
                const int ii = i + 2;
                sd2 = (ii < cnt) ? s_sd[w][buf][ii] : s_sd[w][buf ^ 1][ii - cnt];
                x2 = *reinterpret_cast<const float4*>(&g_xcur[(size_t)sd2.x * DD + lane * 4]);
            }

            const u64* ap = reinterpret_cast<const u64*>(&s_attr[w][buf][i * EDIM]);
            u64 ac0 = pack2(bq.x, 0.f), ac1 = pack2(bq.y, 0.f);
            u64 ac2 = pack2(bq.z, 0.f), ac3 = pack2(bq.w, 0.f);
#pragma unroll
            for (int j = 0; j < 8; j++) {
                const u64 aj = ap[j];
                fma2(ac0, aj, wp[j][0]);
                fma2(ac1, aj, wp[j][1]);
                fma2(ac2, aj, wp[j][2]);
                fma2(ac3, aj, wp[j][3]);
            }
            const float2 q0 = unpack2(ac0), q1 = unpack2(ac1);
            const float2 q2 = unpack2(ac2), q3 = unpack2(ac3);
            const float m0 = fmaxf(q0.x + q0.y + x0.x, 0.f);
            const float m1 = fmaxf(q1.x + q1.y + x0.y, 0.f);
            const float m2 = fmaxf(q2.x + q2.y + x0.z, 0.f);
            const float m3 = fmaxf(q3.x + q3.y + x0.w, 0.f);

            if (sd0.y != cur) {
                float* p = &g_agg[(size_t)cur * DD + lane * 4];
                if (firstflush) red_v4(p, acc);
                else *reinterpret_cast<float4*>(p) = acc;
                firstflush = false;
                acc = make_float4(0.f, 0.f, 0.f, 0.f);
                cur = sd0.y;
            }
            acc.x += m0; acc.y += m1; acc.z += m2; acc.w += m3;

            x0 = x1; x1 = x2; sd0 = sd1; sd1 = sd2; gpos++;
        }
        buf ^= 1;
    }
    red_v4(&g_agg[(size_t)cur * DD + lane * 4], acc);
}

// ---------------------------------------------------------------------------
// Node MLP on WMMA bf16 — BYTE-IDENTICAL logic to R13 (so the ncu profile of
// node_l0 at launch #4 characterizes the known 137us/layer configuration).
// ---------------------------------------------------------------------------
__global__ __launch_bounds__(256, 1) void node_wmma(
    const float* __restrict__ w1, const float* __restrict__ b1,
    const float* __restrict__ w2, const float* __restrict__ b2,
    const float* __restrict__ epsp, const float* __restrict__ vn_next,
    const int* __restrict__ batch, int layer)
{
    extern __shared__ __align__(32) char dyn[];
    __nv_bfloat16* sW1h = reinterpret_cast<__nv_bfloat16*>(dyn);
    __nv_bfloat16* sW1l = sW1h + DD * WS;
    __nv_bfloat16* sW2h = sW1l + DD * WS;
    __nv_bfloat16* sW2l = sW2h + DD * WS;
    __nv_bfloat16* sAh  = sW2l + DD * WS;
    __nv_bfloat16* sAl  = sAh + TROWS * WS;
    float* sC = reinterpret_cast<float*>(sAl + TROWS * WS);

    __shared__ float b1s[DD], b2s[DD];
    __shared__ int sB[TROWS];

    const int t = threadIdx.x;
    const int wid = t >> 5;

    for (int idx = t; idx < DD * DD; idx += 256) {
        const int k = idx >> 7, n = idx & 127;
        float v = w1[idx];
        __nv_bfloat16 h = __float2bfloat16(v);
        sW1h[k * WS + n] = h;
        sW1l[k * WS + n] = __float2bfloat16(v - __bfloat162float(h));
        v = w2[idx];
        h = __float2bfloat16(v);
        sW2h[k * WS + n] = h;
        sW2l[k * WS + n] = __float2bfloat16(v - __bfloat162float(h));
    }
    if (t < DD) { b1s[t] = b1[t]; b2s[t] = b2[t]; }
    const float epsv = 1.0f + *epsp;

    const int rs = wid >> 1;
    const int ch = wid & 1;
    const int r0 = rs * 16;
    const int c0 = ch * 64;

    const int col2 = t & 63;
    const int seg = t >> 6;
    float2 vn2 = make_float2(0.f, 0.f);
    if (vn_next) vn2 = *reinterpret_cast<const float2*>(&vn_next[2 * col2]);
    const int zero_agg = (vn_next != nullptr);

    for (int tile = blockIdx.x; tile < NT64; tile += gridDim.x) {
        const int row0 = tile * TROWS;
        __syncthreads();

        for (int i = t; i < TROWS; i += 256)
            sB[i] = (row0 + i < NN) ? batch[row0 + i] : -1;
        for (int i = t; i < TROWS * (DD / 4); i += 256) {
            const int row = i >> 5, c4 = (i & 31) * 4;
            const int grow = row0 + row;
            float4 hv = make_float4(0.f, 0.f, 0.f, 0.f);
            if (grow < NN) {
                const int gi = row0 * (DD / 4) + i;
                const float4 xv = reinterpret_cast<const float4*>(g_xcur)[gi];
                const float4 av = reinterpret_cast<const float4*>(g_agg)[gi];
                hv.x = fmaf(epsv, xv.x, av.x);
                hv.y = fmaf(epsv, xv.y, av.y);
                hv.z = fmaf(epsv, xv.z, av.z);
                hv.w = fmaf(epsv, xv.w, av.w);
                if (zero_agg)
                    reinterpret_cast<float4*>(g_agg)[gi] = make_float4(0.f, 0.f, 0.f, 0.f);
            }
            __nv_bfloat16* ph = &sAh[row * WS + c4];
            __nv_bfloat16* pl = &sAl[row * WS + c4];
            const float f[4] = {hv.x, hv.y, hv.z, hv.w};
#pragma unroll
            for (int j = 0; j < 4; j++) {
                const __nv_bfloat16 hi = __float2bfloat16(f[j]);
                ph[j] = hi;
                pl[j] = __float2bfloat16(f[j] - __bfloat162float(hi));
            }
        }
        __syncthreads();

        {
            wmma::fragment<wmma::accumulator, 16, 16, 16, float> acc[4];
#pragma unroll
            for (int j = 0; j < 4; j++) wmma::fill_fragment(acc[j], 0.f);
#pragma unroll
            for (int p = 0; p < 3; p++) {
                const __nv_bfloat16* As = (p == 2) ? sAl : sAh;
                const __nv_bfloat16* Bs = (p == 1) ? sW1l : sW1h;
                for (int k = 0; k < 8; k++) {
                    wmma::fragment<wmma::matrix_a, 16, 16, 16, __nv_bfloat16, wmma::row_major> af;
                    wmma::load_matrix_sync(af, &As[r0 * WS + k * 16], WS);
#pragma unroll
                    for (int j = 0; j < 4; j++) {
                        wmma::fragment<wmma::matrix_b, 16, 16, 16, __nv_bfloat16, wmma::row_major> bf;
                        wmma::load_matrix_sync(bf, &Bs[k * 16 * WS + c0 + j * 16], WS);
                        wmma::mma_sync(acc[j], af, bf, acc[j]);
                    }
                }
            }
#pragma unroll
            for (int j = 0; j < 4; j++)
                wmma::store_matrix_sync(&sC[r0 * CS + c0 + j * 16], acc[j], CS,
                                        wmma::mem_row_major);
        }
        __syncthreads();

        for (int i = t; i < TROWS * (DD / 2); i += 256) {
            const int row = i >> 6, c2 = (i & 63) * 2;
            const float y0 = fmaxf(sC[row * CS + c2] + b1s[c2], 0.f);
            const float y1 = fmaxf(sC[row * CS + c2 + 1] + b1s[c2 + 1], 0.f);
            const __nv_bfloat16 h0 = __float2bfloat16(y0);
            const __nv_bfloat16 h1 = __float2bfloat16(y1);
            sAh[row * WS + c2] = h0;
            sAh[row * WS + c2 + 1] = h1;
            sAl[row * WS + c2] = __float2bfloat16(y0 - __bfloat162float(h0));
            sAl[row * WS + c2 + 1] = __float2bfloat16(y1 - __bfloat162float(h1));
        }
        __syncthreads();

        {
            wmma::fragment<wmma::accumulator, 16, 16, 16, float> acc[4];
#pragma unroll
            for (int j = 0; j < 4; j++) wmma::fill_fragment(acc[j], 0.f);
#pragma unroll
            for (int p = 0; p < 3; p++) {
                const __nv_bfloat16* As = (p == 2) ? sAl : sAh;
                const __nv_bfloat16* Bs = (p == 1) ? sW2l : sW2h;
                for (int k = 0; k < 8; k++) {
                    wmma::fragment<wmma::matrix_a, 16, 16, 16, __nv_bfloat16, wmma::row_major> af;
                    wmma::load_matrix_sync(af, &As[r0 * WS + k * 16], WS);
#pragma unroll
                    for (int j = 0; j < 4; j++) {
                        wmma::fragment<wmma::matrix_b, 16, 16, 16, __nv_bfloat16, wmma::row_major> bf;
                        wmma::load_matrix_sync(bf, &Bs[k * 16 * WS + c0 + j * 16], WS);
                        wmma::mma_sync(acc[j], af, bf, acc[j]);
                    }
                }
            }
#pragma unroll
            for (int j = 0; j < 4; j++)
                wmma::store_matrix_sync(&sC[r0 * CS + c0 + j * 16], acc[j], CS,
                                        wmma::mem_row_major);
        }
        __syncthreads();

        {
            const float bx = b2s[2 * col2], by = b2s[2 * col2 + 1];
            float px = 0.f, py = 0.f;
            int curb = -1;
            for (int r = 0; r < 16; r++) {
                const int lrow = seg * 16 + r;
                const int grow = row0 + lrow;
                if (grow >= NN) break;
                const float vx = sC[lrow * CS + 2 * col2] + bx;
                const float vy = sC[lrow * CS + 2 * col2 + 1] + by;
                const int b = sB[lrow];
                if (b != curb) {
                    if (curb >= 0)
                        red_v2(&g_pool[curb * JKD + layer * DD + 2 * col2], px, py);
                    curb = b; px = 0.f; py = 0.f;
                }
                px += vx; py += vy;
                if (vn_next)
                    *reinterpret_cast<float2*>(&g_xcur[(size_t)grow * DD + 2 * col2]) =
                        make_float2(vx + vn2.x, vy + vn2.y);
            }
            if (curb >= 0)
                red_v2(&g_pool[curb * JKD + layer * DD + 2 * col2], px, py);
        }
    }
}

// ---------------------------------------------------------------------------
// Head (unchanged; re-zeroes g_pool rows for graph-replay determinism)
// ---------------------------------------------------------------------------
__device__ __forceinline__ float2 block_sum2(float a, float b) {
    __shared__ float2 sred[8];
    const int lane = threadIdx.x & 31, w = threadIdx.x >> 5;
#pragma unroll
    for (int o = 16; o; o >>= 1) {
        a += __shfl_down_sync(0xffffffffu, a, o);
        b += __shfl_down_sync(0xffffffffu, b, o);
    }
    if (lane == 0) sred[w] = make_float2(a, b);
    __syncthreads();
    if (w == 0) {
        float2 s = (lane < 8) ? sred[lane] : make_float2(0.f, 0.f);
#pragma unroll
        for (int o = 4; o; o >>= 1) {
            s.x += __shfl_down_sync(0xffffffffu, s.x, o);
            s.y += __shfl_down_sync(0xffffffffu, s.y, o);
        }
        if (lane == 0) sred[0] = s;
    }
    __syncthreads();
    const float2 r = sred[0];
    __syncthreads();
    return r;
}

__global__ __launch_bounds__(256) void head_kernel(
    const float* __restrict__ w1, const float* __restrict__ b1,
    const float* __restrict__ ga1, const float* __restrict__ be1,
    const float* __restrict__ w2, const float* __restrict__ b2,
    const float* __restrict__ ga2, const float* __restrict__ be2,
    const float* __restrict__ ow, const float* __restrict__ ob,
    float* __restrict__ out)
{
    __shared__ float sg[JKD];
    __shared__ float s1[256];
    const int g = blockIdx.x, t = threadIdx.x;

    for (int i = t; i < JKD; i += 256) {
        sg[i] = g_pool[g * JKD + i];
        g_pool[g * JKD + i] = 0.f;
    }
    __syncthreads();

    float acc = b1[t];
#pragma unroll 4
    for (int k = 0; k < JKD; k++) acc = fmaf(sg[k], w1[k * 256 + t], acc);
    float2 s = block_sum2(acc, acc * acc);
    float mu = s.x * (1.f / 256.f);
    float var = s.y * (1.f / 256.f) - mu * mu;
    s1[t] = fmaxf((acc - mu) * rsqrtf(var + 1e-5f) * ga1[t] + be1[t], 0.f);
    __syncthreads();

    float acc2 = 0.f;
    if (t < 128) {
        acc2 = b2[t];
#pragma unroll 4
        for (int k = 0; k < 256; k++) acc2 = fmaf(s1[k], w2[k * 128 + t], acc2);
    }
    const float cva = (t < 128) ? acc2 : 0.f;
    float2 s2 = block_sum2(cva, cva * cva);
    float mu2 = s2.x * (1.f / 128.f);
    float var2 = s2.y * (1.f / 128.f) - mu2 * mu2;
    float v2 = 0.f;
    if (t < 128) v2 = fmaxf((acc2 - mu2) * rsqrtf(var2 + 1e-5f) * ga2[t] + be2[t], 0.f);

    const float p = (t < 128) ? v2 * ow[t] : 0.f;
    float2 s3 = block_sum2(p, 0.f);
    if (t == 0) out[g] = s3.x + ob[0];
}

// ---------------------------------------------------------------------------
extern "C" void kernel_launch(void* const* d_in, const int* in_sizes, int n_in,
                              void* d_out, int out_size) {
    (void)in_sizes; (void)n_in; (void)out_size;
    const float* x     = (const float*)d_in[0];
    const int*   ei    = (const int*)d_in[1];
    const float* ea    = (const float*)d_in[2];
    const int*   batch = (const int*)d_in[3];
    const float* vn    = (const float*)d_in[4];
    const float* ew    = (const float*)d_in[5];
    const float* ebias = (const float*)d_in[6];
    const float* eps   = (const float*)d_in[7];
    const float* mw1   = (const float*)d_in[8];
    const float* mb1   = (const float*)d_in[9];
    const float* mw2   = (const float*)d_in[10];
    const float* mb2   = (const float*)d_in[11];
    const float* lw1   = (const float*)d_in[12];
    const float* lb1   = (const float*)d_in[13];
    const float* ln1g  = (const float*)d_in[14];
    const float* ln1b  = (const float*)d_in[15];
    const float* lw2   = (const float*)d_in[16];
    const float* lb2   = (const float*)d_in[17];
    const float* ln2g  = (const float*)d_in[18];
    const float* ln2b  = (const float*)d_in[19];
    const float* ow    = (const float*)d_in[20];
    const float* ob    = (const float*)d_in[21];
    float* out = (float*)d_out;

    int nsm = 148;
    cudaDeviceGetAttribute(&nsm, cudaDevAttrMultiProcessorCount, 0);

    const int node_smem = (4 * DD * WS + 2 * TROWS * WS) * 2 + TROWS * CS * 4;
    cudaFuncSetAttribute(node_wmma, cudaFuncAttributeMaxDynamicSharedMemorySize, node_smem);

    // Launch order puts node_l0 at #4 (the launch ncu captures):
    // init(1), edge_l0(2), hist(3), node_l0(4), scan(5), scatter(6),
    // agg_l1(7), node_l1(8), agg_l2(9), node_l2(10), head(11).
    init_kernel<<<(NN * DD / 4 + 255) / 256, 256>>>(x, vn);
    edge_l0_kernel<<<nsm * 2, 256>>>(ei, ea, ew, ebias);
    k_hist<<<(EE + 255) / 256, 256>>>(ei);
    node_wmma<<<nsm, 256, node_smem>>>(mw1, mb1, mw2, mb2, eps,
                                       vn + 1 * DD, batch, 0);
    k_scan_single<<<1, 1024>>>();
    k_scatter<<<(EE + 255) / 256, 256>>>(ei, ea);

    for (int i = 1; i < LLAYERS; i++) {
        agg_kernel<<<nsm * 2, 256>>>(ew + i * EDIM * DD, ebias + i * DD);
        node_wmma<<<nsm, 256, node_smem>>>(
            mw1 + i * DD * DD, mb1 + i * DD,
            mw2 + i * DD * DD, mb2 + i * DD,
            eps + i,
            (i < LLAYERS - 1) ? (vn + (i + 1) * DD) : nullptr,
            batch, i);
    }

    head_kernel<<<GG, 256>>>(lw1, lb1, ln1g, ln1b, lw2, lb2, ln2g, ln2b, ow, ob, out);
}

// round 15
// speedup vs baseline: 1.1433x; 1.1433x over previous
#include <cuda_runtime.h>
#include <cuda_bf16.h>
#include <mma.h>

using namespace nvcuda;

#define NN 50000
#define DD 128
#define EE 600000
#define GG 512
#define LLAYERS 3
#define EDIM 16
#define JKD 384
#define CHUNK 32
#define TROWS 128
#define NODE_T 512
#define NT128 ((NN + TROWS - 1) / TROWS)
#define WS 136   // bf16 smem stride (elems)
#define CS 136   // f32 staging stride

typedef unsigned long long u64;
typedef unsigned int u32;

// Scratch (device globals: no runtime allocation allowed)
__device__ float g_xcur[NN * DD];
__device__ float g_agg[NN * DD];           // zeroed by scatter_init / node each layer
__device__ float g_pool[GG * JKD];         // zeroed by head_kernel each call
__device__ int   g_cnt[NN];                // zeroed by k_scatter_init each call
__device__ int   g_cursor[NN];
__device__ int   g_csr_src[EE];
__device__ int   g_csr_dst[EE];
__device__ float g_csr_ea[(size_t)EE * EDIM];

// ---------------------------------------------------------------------------
// packed f32x2 helpers
// ---------------------------------------------------------------------------
__device__ __forceinline__ u64 pack2(float x, float y) {
    u64 r; asm("mov.b64 %0, {%1, %2};" : "=l"(r) : "f"(x), "f"(y)); return r;
}
__device__ __forceinline__ float2 unpack2(u64 v) {
    float2 r; asm("mov.b64 {%0, %1}, %2;" : "=f"(r.x), "=f"(r.y) : "l"(v)); return r;
}
__device__ __forceinline__ void fma2(u64& d, u64 a, u64 b) {
    asm("fma.rn.f32x2 %0, %1, %2, %0;" : "+l"(d) : "l"(a), "l"(b));
}
__device__ __forceinline__ void red_v4(float* p, float4 v) {
    asm volatile("red.global.add.v4.f32 [%0], {%1,%2,%3,%4};"
                 :: "l"(p), "f"(v.x), "f"(v.y), "f"(v.z), "f"(v.w) : "memory");
}
__device__ __forceinline__ void red_v2(float* p, float x, float y) {
    asm volatile("red.global.add.v2.f32 [%0], {%1,%2};"
                 :: "l"(p), "f"(x), "f"(y) : "memory");
}

// ---------------------------------------------------------------------------
// CSR build. hist(1) -> scan(2) -> scatter_init(3) -> agg (#4).
// g_cnt zeroed by the PREVIOUS call's scatter_init (module-load zero, call 1).
// ---------------------------------------------------------------------------
__global__ void k_hist(const int* __restrict__ ei) {
    int e = blockIdx.x * blockDim.x + threadIdx.x;
    if (e < EE) atomicAdd(&g_cnt[ei[EE + e]], 1);
}

__global__ __launch_bounds__(1024) void k_scan_single() {
    __shared__ int s[1024];
    const int t = threadIdx.x;
    const int per = (NN + 1023) / 1024;
    const int base = t * per;
    int lim = NN - base;
    if (lim < 0) lim = 0;
    if (lim > per) lim = per;
    int loc = 0;
    for (int i = 0; i < lim; i++) loc += g_cnt[base + i];
    s[t] = loc;
    __syncthreads();
#pragma unroll
    for (int o = 1; o < 1024; o <<= 1) {
        int u = (t >= o) ? s[t - o] : 0;
        __syncthreads();
        s[t] += u;
        __syncthreads();
    }
    int run = (t > 0) ? s[t - 1] : 0;
    for (int i = 0; i < lim; i++) {
        const int c = g_cnt[base + i];
        g_cursor[base + i] = run;
        run += c;
    }
}

__global__ void k_scatter_init(const int* __restrict__ ei, const float* __restrict__ ea,
                               const float* __restrict__ x, const float* __restrict__ vn0) {
    int i = blockIdx.x * blockDim.x + threadIdx.x;
    if (i < EE) {
        const int dst = ei[EE + i];
        const int pos = atomicAdd(&g_cursor[dst], 1);
        g_csr_src[pos] = ei[i];
        g_csr_dst[pos] = dst;
        const float4* q = reinterpret_cast<const float4*>(&ea[(size_t)i * EDIM]);
        float4* s = reinterpret_cast<float4*>(&g_csr_ea[(size_t)pos * EDIM]);
        s[0] = q[0]; s[1] = q[1]; s[2] = q[2]; s[3] = q[3];
    }
    if (i < NN) g_cnt[i] = 0;
    if (i < NN * DD / 4) {
        float4 xv = reinterpret_cast<const float4*>(x)[i];
        float4 vv = reinterpret_cast<const float4*>(vn0)[i & 31];
        xv.x += vv.x; xv.y += vv.y; xv.z += vv.z; xv.w += vv.w;
        reinterpret_cast<float4*>(g_xcur)[i] = xv;
        reinterpret_cast<float4*>(g_agg)[i] = make_float4(0.f, 0.f, 0.f, 0.f);
    }
}

// ---------------------------------------------------------------------------
// Aggregation (R8/R11 version, measured 101.5us repeatedly — unchanged)
// ---------------------------------------------------------------------------
__global__ __launch_bounds__(256, 2) void agg_kernel(
    const float* __restrict__ ew, const float* __restrict__ ebias)
{
    __shared__ float s_attr[8][2][CHUNK * EDIM];
    __shared__ int2  s_sd[8][2][CHUNK];

    const int lane = threadIdx.x & 31;
    const int w = threadIdx.x >> 5;

    u64 wp[8][4];
#pragma unroll
    for (int j = 0; j < 8; j++)
#pragma unroll
        for (int c = 0; c < 4; c++)
            wp[j][c] = pack2(ew[(2 * j) * DD + lane * 4 + c],
                             ew[(2 * j + 1) * DD + lane * 4 + c]);
    const float4 bq = *reinterpret_cast<const float4*>(&ebias[lane * 4]);

    const int warp = (blockIdx.x * blockDim.x + threadIdx.x) >> 5;
    const int nw = (gridDim.x * blockDim.x) >> 5;
    const int epw = (EE + nw - 1) / nw;
    const int beg = warp * epw;
    if (beg >= EE) return;
    const int range = ((beg + epw < EE) ? beg + epw : EE) - beg;
    const int nchunks = (range + CHUNK - 1) / CHUNK;

    {
        const int cnt = (range < CHUNK) ? range : CHUNK;
        const float4* src4 = reinterpret_cast<const float4*>(&g_csr_ea[(size_t)beg * EDIM]);
        float4* dst4 = reinterpret_cast<float4*>(&s_attr[w][0][0]);
        for (int i = lane; i < cnt * 4; i += 32) dst4[i] = src4[i];
        if (lane < cnt) s_sd[w][0][lane] = make_int2(g_csr_src[beg + lane], g_csr_dst[beg + lane]);
    }
    __syncwarp();

    int2 sd0 = s_sd[w][0][0];
    int2 sd1 = (range > 1) ? s_sd[w][0][1] : sd0;
    float4 x0 = *reinterpret_cast<const float4*>(&g_xcur[(size_t)sd0.x * DD + lane * 4]);
    float4 x1 = (range > 1)
        ? *reinterpret_cast<const float4*>(&g_xcur[(size_t)sd1.x * DD + lane * 4]) : x0;

    float4 acc = make_float4(0.f, 0.f, 0.f, 0.f);
    int cur = sd0.y;
    bool firstflush = true;
    int gpos = 0;
    int buf = 0;

    for (int c = 0; c < nchunks; c++) {
        const int cbeg = c * CHUNK;
        const int cnt = ((range - cbeg) < CHUNK) ? (range - cbeg) : CHUNK;

        __syncwarp();
        if (c + 1 < nchunks) {
            const int nbeg = beg + cbeg + CHUNK;
            const int ncnt = ((range - cbeg - CHUNK) < CHUNK) ? (range - cbeg - CHUNK) : CHUNK;
            const float4* src4 = reinterpret_cast<const float4*>(&g_csr_ea[(size_t)nbeg * EDIM]);
            float4* dst4 = reinterpret_cast<float4*>(&s_attr[w][buf ^ 1][0]);
            for (int i = lane; i < ncnt * 4; i += 32) dst4[i] = src4[i];
            if (lane < ncnt)
                s_sd[w][buf ^ 1][lane] = make_int2(g_csr_src[nbeg + lane], g_csr_dst[nbeg + lane]);
        }
        __syncwarp();

        for (int i = 0; i < cnt; i++) {
            int2 sd2 = sd1;
            float4 x2 = make_float4(0.f, 0.f, 0.f, 0.f);
            if (gpos + 2 < range) {
                const int ii = i + 2;
                sd2 = (ii < cnt) ? s_sd[w][buf][ii] : s_sd[w][buf ^ 1][ii - cnt];
                x2 = *reinterpret_cast<const float4*>(&g_xcur[(size_t)sd2.x * DD + lane * 4]);
            }

            const u64* ap = reinterpret_cast<const u64*>(&s_attr[w][buf][i * EDIM]);
            u64 ac0 = pack2(bq.x, 0.f), ac1 = pack2(bq.y, 0.f);
            u64 ac2 = pack2(bq.z, 0.f), ac3 = pack2(bq.w, 0.f);
#pragma unroll
            for (int j = 0; j < 8; j++) {
                const u64 aj = ap[j];
                fma2(ac0, aj, wp[j][0]);
                fma2(ac1, aj, wp[j][1]);
                fma2(ac2, aj, wp[j][2]);
                fma2(ac3, aj, wp[j][3]);
            }
            const float2 q0 = unpack2(ac0), q1 = unpack2(ac1);
            const float2 q2 = unpack2(ac2), q3 = unpack2(ac3);
            const float m0 = fmaxf(q0.x + q0.y + x0.x, 0.f);
            const float m1 = fmaxf(q1.x + q1.y + x0.y, 0.f);
            const float m2 = fmaxf(q2.x + q2.y + x0.z, 0.f);
            const float m3 = fmaxf(q3.x + q3.y + x0.w, 0.f);

            if (sd0.y != cur) {
                float* p = &g_agg[(size_t)cur * DD + lane * 4];
                if (firstflush) red_v4(p, acc);
                else *reinterpret_cast<float4*>(p) = acc;
                firstflush = false;
                acc = make_float4(0.f, 0.f, 0.f, 0.f);
                cur = sd0.y;
            }
            acc.x += m0; acc.y += m1; acc.z += m2; acc.w += m3;

            x0 = x1; x1 = x2; sd0 = sd1; sd1 = sd2; gpos++;
        }
        buf ^= 1;
    }
    red_v4(&g_agg[(size_t)cur * DD + lane * 4], acc);
}

// ---------------------------------------------------------------------------
// Node MLP on WMMA bf16, restructured for latency hiding (R14 profile showed
// occ 12.5%, issue 10.7% — phase-serialization bound):
//  * 512 threads (16 warps = 4/SMSP), 128-row tiles (2x rows per sync chain)
//  * GEMM accumulators kept in REGISTERS across the A->C transition so the
//    f32 C staging ALIASES the bf16 A hi/lo region (both 69.6 KB): smem fits
//    weights(139KB)+R(69.6KB) = 204KB at 1 CTA/SM with double the warps.
//  * convert phase: read C into 32 regs -> syncthreads -> write A (alias-safe)
// ---------------------------------------------------------------------------
__global__ __launch_bounds__(NODE_T, 1) void node_wmma(
    const float* __restrict__ w1, const float* __restrict__ b1,
    const float* __restrict__ w2, const float* __restrict__ b2,
    const float* __restrict__ epsp, const float* __restrict__ vn_next,
    const int* __restrict__ batch, int layer)
{
    extern __shared__ __align__(32) char dyn[];
    __nv_bfloat16* sW1h = reinterpret_cast<__nv_bfloat16*>(dyn);
    __nv_bfloat16* sW1l = sW1h + DD * WS;
    __nv_bfloat16* sW2h = sW1l + DD * WS;
    __nv_bfloat16* sW2l = sW2h + DD * WS;
    __nv_bfloat16* sAh  = sW2l + DD * WS;               // R region as A-hi
    __nv_bfloat16* sAl  = sAh + TROWS * WS;             // R region as A-lo
    float* sC = reinterpret_cast<float*>(sAh);          // R region as C (ALIAS)

    __shared__ float b1s[DD], b2s[DD];
    __shared__ int sB[TROWS];

    const int t = threadIdx.x;
    const int wid = t >> 5;

    // weights hi/lo, once per kernel
    for (int idx = t; idx < DD * DD; idx += NODE_T) {
        const int k = idx >> 7, n = idx & 127;
        float v = w1[idx];
        __nv_bfloat16 h = __float2bfloat16(v);
        sW1h[k * WS + n] = h;
        sW1l[k * WS + n] = __float2bfloat16(v - __bfloat162float(h));
        v = w2[idx];
        h = __float2bfloat16(v);
        sW2h[k * WS + n] = h;
        sW2l[k * WS + n] = __float2bfloat16(v - __bfloat162float(h));
    }
    if (t < DD) { b1s[t] = b1[t]; b2s[t] = b2[t]; }
    const float epsv = 1.0f + *epsp;

    // warp tile: 8 row-stripes x 2 col-halves; 16 rows x 64 cols per warp
    const int r0 = (wid >> 1) * 16;
    const int c0 = (wid & 1) * 64;

    // convert-phase mapping: thread t owns col (t&127), rows (t>>7) + 4*j
    const int ccol = t & 127;
    const int crow0 = t >> 7;

    // epilogue: thread t -> cols {2*col2, 2*col2+1}, rows [seg*16, seg*16+16)
    const int col2 = t & 63;
    const int seg = t >> 6;            // 0..7
    float2 vn2 = make_float2(0.f, 0.f);
    if (vn_next) vn2 = *reinterpret_cast<const float2*>(&vn_next[2 * col2]);
    const int zero_agg = (vn_next != nullptr);

    for (int tile = blockIdx.x; tile < NT128; tile += gridDim.x) {
        const int row0 = tile * TROWS;
        __syncthreads();   // R-region reuse guard across tiles

        // ---- stage h = (1+eps)x + agg -> split into A (R region); batch ----
        for (int i = t; i < TROWS; i += NODE_T)
            sB[i] = (row0 + i < NN) ? batch[row0 + i] : -1;
        for (int i = t; i < TROWS * (DD / 4); i += NODE_T) {
            const int row = i >> 5, c4 = (i & 31) * 4;
            const int grow = row0 + row;
            float4 hv = make_float4(0.f, 0.f, 0.f, 0.f);
            if (grow < NN) {
                const int gi = row0 * (DD / 4) + i;
                const float4 xv = reinterpret_cast<const float4*>(g_xcur)[gi];
                const float4 av = reinterpret_cast<const float4*>(g_agg)[gi];
                hv.x = fmaf(epsv, xv.x, av.x);
                hv.y = fmaf(epsv, xv.y, av.y);
                hv.z = fmaf(epsv, xv.z, av.z);
                hv.w = fmaf(epsv, xv.w, av.w);
                if (zero_agg)
                    reinterpret_cast<float4*>(g_agg)[gi] = make_float4(0.f, 0.f, 0.f, 0.f);
            }
            __nv_bfloat16* ph = &sAh[row * WS + c4];
            __nv_bfloat16* pl = &sAl[row * WS + c4];
            const float f[4] = {hv.x, hv.y, hv.z, hv.w};
#pragma unroll
            for (int j = 0; j < 4; j++) {
                const __nv_bfloat16 hi = __float2bfloat16(f[j]);
                ph[j] = hi;
                pl[j] = __float2bfloat16(f[j] - __bfloat162float(hi));
            }
        }
        __syncthreads();

        // ---- GEMM1 (acc stays in registers) ----
        wmma::fragment<wmma::accumulator, 16, 16, 16, float> acc[4];
#pragma unroll
        for (int j = 0; j < 4; j++) wmma::fill_fragment(acc[j], 0.f);
#pragma unroll
        for (int p = 0; p < 3; p++) {
            const __nv_bfloat16* As = (p == 2) ? sAl : sAh;
            const __nv_bfloat16* Bs = (p == 1) ? sW1l : sW1h;
            for (int k = 0; k < 8; k++) {
                wmma::fragment<wmma::matrix_a, 16, 16, 16, __nv_bfloat16, wmma::row_major> af;
                wmma::load_matrix_sync(af, &As[r0 * WS + k * 16], WS);
#pragma unroll
                for (int j = 0; j < 4; j++) {
                    wmma::fragment<wmma::matrix_b, 16, 16, 16, __nv_bfloat16, wmma::row_major> bf;
                    wmma::load_matrix_sync(bf, &Bs[k * 16 * WS + c0 + j * 16], WS);
                    wmma::mma_sync(acc[j], af, bf, acc[j]);
                }
            }
        }
        __syncthreads();   // all warps finished READING A -> safe to overwrite R as C
#pragma unroll
        for (int j = 0; j < 4; j++)
            wmma::store_matrix_sync(&sC[r0 * CS + c0 + j * 16], acc[j], CS,
                                    wmma::mem_row_major);
        __syncthreads();

        // ---- y = relu(C + b1): read into regs, sync, write split A ----
        {
            float yreg[32];
#pragma unroll
            for (int j = 0; j < 32; j++) {
                const int row = crow0 + j * 4;
                yreg[j] = fmaxf(sC[row * CS + ccol] + b1s[ccol], 0.f);
            }
            __syncthreads();   // all C reads done -> safe to overwrite R as A
#pragma unroll
            for (int j = 0; j < 32; j++) {
                const int row = crow0 + j * 4;
                const __nv_bfloat16 h = __float2bfloat16(yreg[j]);
                sAh[row * WS + ccol] = h;
                sAl[row * WS + ccol] = __float2bfloat16(yreg[j] - __bfloat162float(h));
            }
        }
        __syncthreads();

        // ---- GEMM2 (acc in registers) ----
#pragma unroll
        for (int j = 0; j < 4; j++) wmma::fill_fragment(acc[j], 0.f);
#pragma unroll
        for (int p = 0; p < 3; p++) {
            const __nv_bfloat16* As = (p == 2) ? sAl : sAh;
            const __nv_bfloat16* Bs = (p == 1) ? sW2l : sW2h;
            for (int k = 0; k < 8; k++) {
                wmma::fragment<wmma::matrix_a, 16, 16, 16, __nv_bfloat16, wmma::row_major> af;
                wmma::load_matrix_sync(af, &As[r0 * WS + k * 16], WS);
#pragma unroll
                for (int j = 0; j < 4; j++) {
                    wmma::fragment<wmma::matrix_b, 16, 16, 16, __nv_bfloat16, wmma::row_major> bf;
                    wmma::load_matrix_sync(bf, &Bs[k * 16 * WS + c0 + j * 16], WS);
                    wmma::mma_sync(acc[j], af, bf, acc[j]);
                }
            }
        }
        __syncthreads();   // all A reads done -> overwrite R as C
#pragma unroll
        for (int j = 0; j < 4; j++)
            wmma::store_matrix_sync(&sC[r0 * CS + c0 + j * 16], acc[j], CS,
                                    wmma::mem_row_major);
        __syncthreads();

        // ---- epilogue: x2 = C + b2; pool RED (run-length); x_cur = x2 + vn ----
        {
            const float bx = b2s[2 * col2], by = b2s[2 * col2 + 1];
            float px = 0.f, py = 0.f;
            int curb = -1;
            for (int r = 0; r < 16; r++) {
                const int lrow = seg * 16 + r;
                const int grow = row0 + lrow;
                if (grow >= NN) break;
                const float vx = sC[lrow * CS + 2 * col2] + bx;
                const float vy = sC[lrow * CS + 2 * col2 + 1] + by;
                const int b = sB[lrow];
                if (b != curb) {
                    if (curb >= 0)
                        red_v2(&g_pool[curb * JKD + layer * DD + 2 * col2], px, py);
                    curb = b; px = 0.f; py = 0.f;
                }
                px += vx; py += vy;
                if (vn_next)
                    *reinterpret_cast<float2*>(&g_xcur[(size_t)grow * DD + 2 * col2]) =
                        make_float2(vx + vn2.x, vy + vn2.y);
            }
            if (curb >= 0)
                red_v2(&g_pool[curb * JKD + layer * DD + 2 * col2], px, py);
        }
    }
}

// ---------------------------------------------------------------------------
// Head (unchanged; re-zeroes g_pool rows for graph-replay determinism)
// ---------------------------------------------------------------------------
__device__ __forceinline__ float2 block_sum2(float a, float b) {
    __shared__ float2 sred[8];
    const int lane = threadIdx.x & 31, w = threadIdx.x >> 5;
#pragma unroll
    for (int o = 16; o; o >>= 1) {
        a += __shfl_down_sync(0xffffffffu, a, o);
        b += __shfl_down_sync(0xffffffffu, b, o);
    }
    if (lane == 0) sred[w] = make_float2(a, b);
    __syncthreads();
    if (w == 0) {
        float2 s = (lane < 8) ? sred[lane] : make_float2(0.f, 0.f);
#pragma unroll
        for (int o = 4; o; o >>= 1) {
            s.x += __shfl_down_sync(0xffffffffu, s.x, o);
            s.y += __shfl_down_sync(0xffffffffu, s.y, o);
        }
        if (lane == 0) sred[0] = s;
    }
    __syncthreads();
    const float2 r = sred[0];
    __syncthreads();
    return r;
}

__global__ __launch_bounds__(256) void head_kernel(
    const float* __restrict__ w1, const float* __restrict__ b1,
    const float* __restrict__ ga1, const float* __restrict__ be1,
    const float* __restrict__ w2, const float* __restrict__ b2,
    const float* __restrict__ ga2, const float* __restrict__ be2,
    const float* __restrict__ ow, const float* __restrict__ ob,
    float* __restrict__ out)
{
    __shared__ float sg[JKD];
    __shared__ float s1[256];
    const int g = blockIdx.x, t = threadIdx.x;

    for (int i = t; i < JKD; i += 256) {
        sg[i] = g_pool[g * JKD + i];
        g_pool[g * JKD + i] = 0.f;
    }
    __syncthreads();

    float acc = b1[t];
#pragma unroll 4
    for (int k = 0; k < JKD; k++) acc = fmaf(sg[k], w1[k * 256 + t], acc);
    float2 s = block_sum2(acc, acc * acc);
    float mu = s.x * (1.f / 256.f);
    float var = s.y * (1.f / 256.f) - mu * mu;
    s1[t] = fmaxf((acc - mu) * rsqrtf(var + 1e-5f) * ga1[t] + be1[t], 0.f);
    __syncthreads();

    float acc2 = 0.f;
    if (t < 128) {
        acc2 = b2[t];
#pragma unroll 4
        for (int k = 0; k < 256; k++) acc2 = fmaf(s1[k], w2[k * 128 + t], acc2);
    }
    const float cva = (t < 128) ? acc2 : 0.f;
    float2 s2 = block_sum2(cva, cva * cva);
    float mu2 = s2.x * (1.f / 128.f);
    float var2 = s2.y * (1.f / 128.f) - mu2 * mu2;
    float v2 = 0.f;
    if (t < 128) v2 = fmaxf((acc2 - mu2) * rsqrtf(var2 + 1e-5f) * ga2[t] + be2[t], 0.f);

    const float p = (t < 128) ? v2 * ow[t] : 0.f;
    float2 s3 = block_sum2(p, 0.f);
    if (t == 0) out[g] = s3.x + ob[0];
}

// ---------------------------------------------------------------------------
extern "C" void kernel_launch(void* const* d_in, const int* in_sizes, int n_in,
                              void* d_out, int out_size) {
    (void)in_sizes; (void)n_in; (void)out_size;
    const float* x     = (const float*)d_in[0];
    const int*   ei    = (const int*)d_in[1];
    const float* ea    = (const float*)d_in[2];
    const int*   batch = (const int*)d_in[3];
    const float* vn    = (const float*)d_in[4];
    const float* ew    = (const float*)d_in[5];
    const float* ebias = (const float*)d_in[6];
    const float* eps   = (const float*)d_in[7];
    const float* mw1   = (const float*)d_in[8];
    const float* mb1   = (const float*)d_in[9];
    const float* mw2   = (const float*)d_in[10];
    const float* mb2   = (const float*)d_in[11];
    const float* lw1   = (const float*)d_in[12];
    const float* lb1   = (const float*)d_in[13];
    const float* ln1g  = (const float*)d_in[14];
    const float* ln1b  = (const float*)d_in[15];
    const float* lw2   = (const float*)d_in[16];
    const float* lb2   = (const float*)d_in[17];
    const float* ln2g  = (const float*)d_in[18];
    const float* ln2b  = (const float*)d_in[19];
    const float* ow    = (const float*)d_in[20];
    const float* ob    = (const float*)d_in[21];
    float* out = (float*)d_out;

    int nsm = 148;
    cudaDeviceGetAttribute(&nsm, cudaDevAttrMultiProcessorCount, 0);

    // weights (4 bufs) + R region (A hi/lo bf16 aliased with C f32)
    const int node_smem = 4 * DD * WS * 2 + TROWS * WS * 2 * 2;   // 208896 B
    cudaFuncSetAttribute(node_wmma, cudaFuncAttributeMaxDynamicSharedMemorySize, node_smem);

    k_hist<<<(EE + 255) / 256, 256>>>(ei);
    k_scan_single<<<1, 1024>>>();
    k_scatter_init<<<(NN * DD / 4 + 255) / 256, 256>>>(ei, ea, x, vn);

    for (int i = 0; i < LLAYERS; i++) {
        agg_kernel<<<nsm * 2, 256>>>(ew + i * EDIM * DD, ebias + i * DD);
        node_wmma<<<nsm, NODE_T, node_smem>>>(
            mw1 + i * DD * DD, mb1 + i * DD,
            mw2 + i * DD * DD, mb2 + i * DD,
            eps + i,
            (i < LLAYERS - 1) ? (vn + (i + 1) * DD) : nullptr,
            batch, i);
    }

    head_kernel<<<GG, 256>>>(lw1, lb1, ln1g, ln1b, lw2, lb2, ln2g, ln2b, ow, ob, out);
}